// round 13
// baseline (speedup 1.0000x reference)
#include <cuda_runtime.h>
#include <cuda_fp16.h>

#define N_NODES 50000
#define E_EDGES 800000
#define D 128
#define KDIM 512
#define CAP 96
#define OVF_CAP 4096

typedef unsigned long long u64;
typedef unsigned int u32;

// Scratch (allocation-free rule: __device__ globals)
// g_Xh/g_Xl: [node][512] split-fp16 X, 128B per 64-col chunk, pre-permuted
// by (node & 7) so the GEMM smem fill is a straight 16B copy.
__device__ __half g_Xh[(size_t)50176 * KDIM];
__device__ __half g_Xl[(size_t)50176 * KDIM];
__device__ __half g_Wh[8 * 8192];          // [chunk][n][64] pre-permuted fp16
__device__ u64 g_rec[(size_t)N_NODES * CAP];
__device__ int g_cnt[N_NODES + 1];         // [N_NODES] = overflow count
__device__ int4 g_ovf[OVF_CAP];

__device__ __forceinline__ u32 pack_half2(float a, float b) {
    __half h0 = __float2half(a);
    __half h1 = __float2half(b);
    return (u32)__half_as_ushort(h0) | ((u32)__half_as_ushort(h1) << 16);
}

// ---------------------------------------------------------------------------
// prepfill: ONE kernel = edge bucketing + X-split(h chunks 0-1) + W prep.
// Counters are zero at launch start (zero-init at load; reset by agg/gemm).
// ---------------------------------------------------------------------------
#define PF_FILL E_EDGES                    // [0, 800000) edges
#define PF_H (PF_FILL + 1600000)           // 50000*32 float4 units of h
#define PF_END (PF_H + 65536)              // 128*512 W elements

__global__ void prepfill_kernel(const float* __restrict__ h,
                                const float* __restrict__ W,
                                const float* __restrict__ dist,
                                const int* __restrict__ src,
                                const int* __restrict__ dst,
                                const int* __restrict__ pos) {
    int i = blockIdx.x * blockDim.x + threadIdx.x;
    if (i < PF_FILL) {
        int e = i;
        int p = pos[e];
        if (p >= 3) return;
        int d = dst[e];
        int s = src[e];
        float w = dist[e];
        int slot = atomicAdd(&g_cnt[d], 1);
        if (slot < CAP) {
            unsigned lo = (unsigned)s | ((unsigned)p << 16);
            unsigned hi = __float_as_uint(w);
            g_rec[(size_t)d * CAP + slot] = (u64)lo | ((u64)hi << 32);
        } else {
            int o = atomicAdd(&g_cnt[N_NODES], 1);
            if (o < OVF_CAP) g_ovf[o] = make_int4(s, d, p, __float_as_int(w));
        }
    } else if (i < PF_H) {
        int i2 = i - PF_FILL;
        int node = i2 >> 5;
        int j = i2 & 31;                    // float4 index within row
        float4 f = ((const float4*)h)[(size_t)node * 32 + j];
        float ff[4] = {f.x, f.y, f.z, f.w};
        u32 hw[2], lw[2];
#pragma unroll
        for (int q = 0; q < 2; q++) {
            float a = ff[2 * q], b = ff[2 * q + 1];
            __half h0 = __float2half(a);
            __half h1 = __float2half(b);
            hw[q] = (u32)__half_as_ushort(h0) | ((u32)__half_as_ushort(h1) << 16);
            lw[q] = pack_half2(a - __half2float(h0), b - __half2float(h1));
        }
        int chunk = j >> 4;
        int jj = j & 15;
        int u = jj >> 1, half = jj & 1;
        size_t db = (size_t)node * 1024 + chunk * 128 + ((u ^ (node & 7)) << 4) + half * 8;
        *(uint2*)((char*)g_Xh + db) = make_uint2(hw[0], hw[1]);
        *(uint2*)((char*)g_Xl + db) = make_uint2(lw[0], lw[1]);
    } else if (i < PF_END) {
        int i2 = i - PF_H;
        int n = i2 >> 9;
        int c = i2 & 511;
        float v = W[n * 640 + c];
        if (c >= 128 && c < 256) v += W[n * 640 + c + 384];
        int chunk = c >> 6, kk = c & 63;
        int u = kk >> 3, sub = kk & 7;
        size_t db = (size_t)chunk * 16384 + n * 128 + ((u ^ (n & 7)) << 4) + sub * 2;
        *(__half*)((char*)g_Wh + db) = __float2half(v);
    }
}

// ---------------------------------------------------------------------------
// Aggregation: one warp per dst node; 3 direction channels in registers.
// Gathers fp16 h from g_Xh chunks 0-1 (8B/lane instead of 16B -> half the
// L2 gather traffic). Overflow fixup uses the fp32 h path (tiny).
// Output: split-fp16 X chunks 2-7 (pre-permuted). Resets g_cnt[d].
// ---------------------------------------------------------------------------
__global__ __launch_bounds__(256) void agg_kernel(const float4* __restrict__ h4) {
    int idx = blockIdx.x * blockDim.x + threadIdx.x;
    int d = idx >> 5;
    int lane = idx & 31;
    if (d >= N_NODES) return;
    int deg = g_cnt[d];
    float4 a[3];
#pragma unroll
    for (int p = 0; p < 3; p++) a[p] = make_float4(0.f, 0.f, 0.f, 0.f);

    // lane covers cols lane*4 .. lane*4+3 -> fp16 location in g_Xh chunks 0/1
    const int gchunk = lane >> 4;            // 0: cols 0-63, 1: cols 64-127
    const int gu = (lane & 15) >> 1;         // 16B unit within chunk
    const int ghalf = lane & 1;              // 8B half within unit
    const int gbase = gchunk * 128 + ghalf * 8;

    const u64* rp = g_rec + (size_t)d * CAP;
    int nrec = deg > CAP ? CAP : deg;
#pragma unroll 4
    for (int i = 0; i < nrec; i++) {
        u64 rec = __ldg(rp + i);
        unsigned lo = (unsigned)rec;
        float w = __uint_as_float((unsigned)(rec >> 32));
        int s = lo & 0xFFFF;
        int p = lo >> 16;
        size_t off = (size_t)s * 1024 + gbase + (size_t)((gu ^ (s & 7)) << 4);
        uint2 v = *(const uint2*)((const char*)g_Xh + off);
        float2 f01 = __half22float2(*reinterpret_cast<__half2*>(&v.x));
        float2 f23 = __half22float2(*reinterpret_cast<__half2*>(&v.y));
        if (p == 0)      { a[0].x += f01.x * w; a[0].y += f01.y * w; a[0].z += f23.x * w; a[0].w += f23.y * w; }
        else if (p == 1) { a[1].x += f01.x * w; a[1].y += f01.y * w; a[1].z += f23.x * w; a[1].w += f23.y * w; }
        else             { a[2].x += f01.x * w; a[2].y += f01.y * w; a[2].z += f23.x * w; a[2].w += f23.y * w; }
    }
    if (deg > CAP) {   // inline overflow fixup (normally zero iterations)
        int n = g_cnt[N_NODES];
        if (n > OVF_CAP) n = OVF_CAP;
        for (int i = 0; i < n; i++) {
            int4 r = g_ovf[i];
            if (r.y != d) continue;
            float w = __int_as_float(r.w);
            float4 hv = h4[(size_t)r.x * 32 + lane];
            int p = r.z;
            if (p == 0)      { a[0].x += hv.x * w; a[0].y += hv.y * w; a[0].z += hv.z * w; a[0].w += hv.w * w; }
            else if (p == 1) { a[1].x += hv.x * w; a[1].y += hv.y * w; a[1].z += hv.z * w; a[1].w += hv.w * w; }
            else             { a[2].x += hv.x * w; a[2].y += hv.y * w; a[2].z += hv.z * w; a[2].w += hv.w * w; }
        }
    }
    if (lane == 0) g_cnt[d] = 0;   // clean slate for next launch

    int chunkBase = 2 + (lane >> 4);
    int u = (lane & 15) >> 1, half = lane & 1;
    size_t db0 = (size_t)d * 1024 + ((u ^ (d & 7)) << 4) + half * 8;
#pragma unroll
    for (int p = 0; p < 3; p++) {
        float ff[4] = {a[p].x, a[p].y, a[p].z, a[p].w};
        u32 hw[2], lw[2];
#pragma unroll
        for (int q = 0; q < 2; q++) {
            float av = ff[2 * q], bv = ff[2 * q + 1];
            __half h0 = __float2half(av);
            __half h1 = __float2half(bv);
            hw[q] = (u32)__half_as_ushort(h0) | ((u32)__half_as_ushort(h1) << 16);
            lw[q] = pack_half2(av - __half2float(h0), bv - __half2float(h1));
        }
        size_t db = db0 + (chunkBase + 2 * p) * 128;
        *(uint2*)((char*)g_Xh + db) = make_uint2(hw[0], hw[1]);
        *(uint2*)((char*)g_Xl + db) = make_uint2(lw[0], lw[1]);
    }
}

// ---------------------------------------------------------------------------
// Split-fp16 mma.sync GEMM + bias + LayerNorm + ReLU.
// z = Xh*Wh + Xl*Wh (W single fp16; X split hi/lo). 2 MMA passes.
// CTA 128x128, 8 warps 4(M)x2(N), X AND B double-buffered, 2 CTAs/SM.
// ---------------------------------------------------------------------------
#define SM_BIAS 0
#define SM_GAMMA 512
#define SM_BETA 1024
#define SM_ROWS 1536
#define SM_X 3584                       // 2 bufs x (Xh 16K | Xl 16K)
#define SM_B (SM_X + 65536)             // 2 bufs x (Wh 16K)
#define SMEM_GEMM (SM_B + 32768)        // 101888 B

__device__ __forceinline__ void mma_f16(float* c, u32 a0, u32 a1, u32 a2, u32 a3,
                                        u32 b0, u32 b1) {
    asm volatile(
        "mma.sync.aligned.m16n8k16.row.col.f32.f16.f16.f32 "
        "{%0,%1,%2,%3}, {%4,%5,%6,%7}, {%8,%9}, {%0,%1,%2,%3};"
        : "+f"(c[0]), "+f"(c[1]), "+f"(c[2]), "+f"(c[3])
        : "r"(a0), "r"(a1), "r"(a2), "r"(a3), "r"(b0), "r"(b1));
}
#define LDSM4(r0, r1, r2, r3, addr) \
    asm volatile("ldmatrix.sync.aligned.m8n8.x4.shared.b16 {%0,%1,%2,%3}, [%4];" \
                 : "=r"(r0), "=r"(r1), "=r"(r2), "=r"(r3) : "r"(addr))
#define CP16(dst, src) \
    asm volatile("cp.async.cg.shared.global [%0], [%1], 16;" :: "r"(dst), "l"(src))
#define CP_COMMIT() asm volatile("cp.async.commit_group;" ::: "memory")
#define CP_WAIT1() asm volatile("cp.async.wait_group 1;" ::: "memory")
#define CP_WAIT0() asm volatile("cp.async.wait_group 0;" ::: "memory")

__device__ __forceinline__ u32 smem_u32(const void* p) {
    u32 a;
    asm("{ .reg .u64 t; cvta.to.shared.u64 t, %1; cvt.u32.u64 %0, t; }"
        : "=r"(a) : "l"(p));
    return a;
}

__global__ __launch_bounds__(256, 2) void gemm_ln_kernel(
    const float* __restrict__ bias,
    const float* __restrict__ gamma,
    const float* __restrict__ beta,
    float* __restrict__ out) {

    extern __shared__ char smem[];
    const u32 sbase = smem_u32(smem);
    const int tid = threadIdx.x;
    const int lane = tid & 31;
    const int wid = tid >> 5;
    const int warpM = wid >> 1;
    const int warpN = wid & 1;
    const int nodeBase = blockIdx.x * 128;
    const int laneRow = lane >> 2;
    const int laneK2 = (lane & 3) * 2;
    const int lr = lane & 7;
    const int lg = lane >> 3;

    if (blockIdx.x == 0 && tid == 0) g_cnt[N_NODES] = 0;  // reset overflow ctr

    const int aRowB = warpM * 32 + (lg & 1) * 8 + lr;
    const int aUG = lg >> 1;
    const int aSw = aRowB & 7;
    const int bRowB = warpN * 64 + (lg >> 1) * 8 + lr;
    const int bUG = lg & 1;
    const int bSw = bRowB & 7;

    if (tid < 128) {
        *(float*)(smem + SM_BIAS + tid * 4) = bias[tid];
        *(float*)(smem + SM_GAMMA + tid * 4) = gamma[tid];
        *(float*)(smem + SM_BETA + tid * 4) = beta[tid];
    }

    float acc[2][8][4];
#pragma unroll
    for (int mt = 0; mt < 2; mt++)
#pragma unroll
        for (int nt = 0; nt < 8; nt++)
#pragma unroll
            for (int q = 0; q < 4; q++) acc[mt][nt][q] = 0.f;

    const size_t xrowbase = (size_t)nodeBase * 1024;
    auto issue_chunk = [&](int c) {
        int buf = c & 1;
        u32 dx = sbase + SM_X + buf * 32768;
#pragma unroll
        for (int it = 0; it < 4; it++) {
            int u = tid + it * 256;          // 0..1023 16B units
            int row = u >> 3, un = u & 7;
            size_t so = xrowbase + (size_t)row * 1024 + c * 128 + un * 16;
            CP16(dx + row * 128 + un * 16, (const char*)g_Xh + so);
            CP16(dx + 16384 + row * 128 + un * 16, (const char*)g_Xl + so);
        }
        u32 db = sbase + SM_B + buf * 16384;
#pragma unroll
        for (int it = 0; it < 4; it++) {
            int u = tid + it * 256;          // 0..1023 16B units
            size_t so = (size_t)c * 16384 + u * 16;
            CP16(db + u * 16, (const char*)g_Wh + so);
        }
        CP_COMMIT();
    };

    issue_chunk(0);
    issue_chunk(1);

    for (int c = 0; c < 8; c++) {
        if (c < 7) CP_WAIT1(); else CP_WAIT0();
        __syncthreads();

        const u32 xh = sbase + SM_X + (c & 1) * 32768;
        const u32 xl = xh + 16384;
        const u32 bh = sbase + SM_B + (c & 1) * 16384;
#pragma unroll
        for (int ks = 0; ks < 4; ks++) {
            u32 ah[2][4], al[2][4], bf[8][2];
            const int aCol = ((2 * ks + aUG) ^ aSw) << 4;
            const int bCol = ((2 * ks + bUG) ^ bSw) << 4;
#pragma unroll
            for (int mt = 0; mt < 2; mt++) {
                u32 ro = (u32)((aRowB + mt * 16) * 128 + aCol);
                LDSM4(ah[mt][0], ah[mt][1], ah[mt][2], ah[mt][3], xh + ro);
            }
#pragma unroll
            for (int mt = 0; mt < 2; mt++) {
                u32 ro = (u32)((aRowB + mt * 16) * 128 + aCol);
                LDSM4(al[mt][0], al[mt][1], al[mt][2], al[mt][3], xl + ro);
            }
#pragma unroll
            for (int ntp = 0; ntp < 4; ntp++) {
                u32 ro = (u32)((bRowB + ntp * 16) * 128 + bCol);
                LDSM4(bf[2 * ntp][0], bf[2 * ntp][1],
                      bf[2 * ntp + 1][0], bf[2 * ntp + 1][1], bh + ro);
            }
#pragma unroll
            for (int mt = 0; mt < 2; mt++)
#pragma unroll
                for (int nt = 0; nt < 8; nt++)
                    mma_f16(acc[mt][nt], ah[mt][0], ah[mt][1], ah[mt][2], ah[mt][3],
                            bf[nt][0], bf[nt][1]);
#pragma unroll
            for (int mt = 0; mt < 2; mt++)
#pragma unroll
                for (int nt = 0; nt < 8; nt++)
                    mma_f16(acc[mt][nt], al[mt][0], al[mt][1], al[mt][2], al[mt][3],
                            bf[nt][0], bf[nt][1]);
        }
        __syncthreads();
        if (c < 6) issue_chunk(c + 2);
    }

    // ---- Epilogue: bias + LN sums from fragments ----
    const float* sbias = (const float*)(smem + SM_BIAS);
    float s1[2][2], s2[2][2];
#pragma unroll
    for (int mt = 0; mt < 2; mt++) { s1[mt][0] = s1[mt][1] = s2[mt][0] = s2[mt][1] = 0.f; }
#pragma unroll
    for (int mt = 0; mt < 2; mt++)
#pragma unroll
        for (int nt = 0; nt < 8; nt++) {
            int j0 = warpN * 64 + nt * 8 + laneK2;
            float b0 = sbias[j0], b1 = sbias[j0 + 1];
            acc[mt][nt][0] += b0; acc[mt][nt][1] += b1;
            acc[mt][nt][2] += b0; acc[mt][nt][3] += b1;
            s1[mt][0] += acc[mt][nt][0] + acc[mt][nt][1];
            s2[mt][0] += acc[mt][nt][0] * acc[mt][nt][0] + acc[mt][nt][1] * acc[mt][nt][1];
            s1[mt][1] += acc[mt][nt][2] + acc[mt][nt][3];
            s2[mt][1] += acc[mt][nt][2] * acc[mt][nt][2] + acc[mt][nt][3] * acc[mt][nt][3];
        }
#pragma unroll
    for (int mt = 0; mt < 2; mt++)
#pragma unroll
        for (int rh = 0; rh < 2; rh++) {
            s1[mt][rh] += __shfl_xor_sync(0xFFFFFFFF, s1[mt][rh], 1);
            s1[mt][rh] += __shfl_xor_sync(0xFFFFFFFF, s1[mt][rh], 2);
            s2[mt][rh] += __shfl_xor_sync(0xFFFFFFFF, s2[mt][rh], 1);
            s2[mt][rh] += __shfl_xor_sync(0xFFFFFFFF, s2[mt][rh], 2);
        }
    if ((lane & 3) == 0) {
#pragma unroll
        for (int mt = 0; mt < 2; mt++)
#pragma unroll
            for (int rh = 0; rh < 2; rh++) {
                int row = warpM * 32 + mt * 16 + rh * 8 + laneRow;
                *(float2*)(smem + SM_ROWS + (warpN * 128 + row) * 8) =
                    make_float2(s1[mt][rh], s2[mt][rh]);
            }
    }
    __syncthreads();

    const float* sg = (const float*)(smem + SM_GAMMA);
    const float* sbeta = (const float*)(smem + SM_BETA);
#pragma unroll
    for (int mt = 0; mt < 2; mt++)
#pragma unroll
        for (int rh = 0; rh < 2; rh++) {
            int row = warpM * 32 + mt * 16 + rh * 8 + laneRow;
            float2 p0 = *(const float2*)(smem + SM_ROWS + row * 8);
            float2 p1 = *(const float2*)(smem + SM_ROWS + (128 + row) * 8);
            float mu = (p0.x + p1.x) * (1.0f / 128.0f);
            float var = (p0.y + p1.y) * (1.0f / 128.0f) - mu * mu;
            float rs = rsqrtf(var + 1e-5f);
            int gn = nodeBase + row;
            if (gn < N_NODES) {
#pragma unroll
                for (int nt = 0; nt < 8; nt++) {
                    int j0 = warpN * 64 + nt * 8 + laneK2;
                    float z0 = acc[mt][nt][rh * 2 + 0];
                    float z1 = acc[mt][nt][rh * 2 + 1];
                    float2 o;
                    o.x = fmaxf((z0 - mu) * rs * sg[j0] + sbeta[j0], 0.f);
                    o.y = fmaxf((z1 - mu) * rs * sg[j0 + 1] + sbeta[j0 + 1], 0.f);
                    *(float2*)(out + (size_t)gn * 128 + j0) = o;
                }
            }
        }
}

extern "C" void kernel_launch(void* const* d_in, const int* in_sizes, int n_in,
                              void* d_out, int out_size) {
    const float* h     = (const float*)d_in[0];
    const float* dist  = (const float*)d_in[1];
    const float* W     = (const float*)d_in[2];
    const float* b     = (const float*)d_in[3];
    const float* gamma = (const float*)d_in[4];
    const float* beta  = (const float*)d_in[5];
    const int* src     = (const int*)d_in[6];
    const int* dst     = (const int*)d_in[7];
    const int* pos     = (const int*)d_in[8];
    float* out = (float*)d_out;

    cudaFuncSetAttribute(gemm_ln_kernel,
                         cudaFuncAttributeMaxDynamicSharedMemorySize, SMEM_GEMM);

    prepfill_kernel<<<(PF_END + 255) / 256, 256>>>(h, W, dist, src, dst, pos);

    agg_kernel<<<(N_NODES * 32 + 255) / 256, 256>>>((const float4*)h);

    gemm_ln_kernel<<<(N_NODES + 127) / 128, 256, SMEM_GEMM>>>(b, gamma, beta, out);
}

// round 14
// speedup vs baseline: 1.8598x; 1.8598x over previous
#include <cuda_runtime.h>
#include <cuda_fp16.h>

#define N_NODES 50000
#define E_EDGES 800000
#define D 128
#define KDIM 512
#define CAP 96
#define OVF_CAP 4096

typedef unsigned long long u64;
typedef unsigned int u32;

// Scratch (allocation-free rule: __device__ globals)
// g_Xh: [node][512] fp16 X, 128B per 64-col chunk, pre-permuted by (node & 7)
// so the GEMM smem fill is a straight 16B copy.
__device__ __half g_Xh[(size_t)50176 * KDIM];
__device__ __half g_Wh[8 * 8192];          // [chunk][n][64] pre-permuted fp16
__device__ u64 g_rec[(size_t)N_NODES * CAP];
__device__ int g_cnt[N_NODES + 1];         // [N_NODES] = overflow count
__device__ int4 g_ovf[OVF_CAP];

// ---------------------------------------------------------------------------
// prepfill: ONE kernel = edge bucketing + X(h chunks 0-1) + W prep.
// Counters are zero at launch start (zero-init at load; reset by agg/gemm).
// ---------------------------------------------------------------------------
#define PF_FILL E_EDGES                    // [0, 800000) edges
#define PF_H (PF_FILL + 1600000)           // 50000*32 float4 units of h
#define PF_END (PF_H + 65536)              // 128*512 W elements

__global__ void prepfill_kernel(const float* __restrict__ h,
                                const float* __restrict__ W,
                                const float* __restrict__ dist,
                                const int* __restrict__ src,
                                const int* __restrict__ dst,
                                const int* __restrict__ pos) {
    int i = blockIdx.x * blockDim.x + threadIdx.x;
    if (i < PF_FILL) {
        int e = i;
        int p = pos[e];
        if (p >= 3) return;
        int d = dst[e];
        int s = src[e];
        float w = dist[e];
        int slot = atomicAdd(&g_cnt[d], 1);
        if (slot < CAP) {
            unsigned lo = (unsigned)s | ((unsigned)p << 16);
            unsigned hi = __float_as_uint(w);
            g_rec[(size_t)d * CAP + slot] = (u64)lo | ((u64)hi << 32);
        } else {
            int o = atomicAdd(&g_cnt[N_NODES], 1);
            if (o < OVF_CAP) g_ovf[o] = make_int4(s, d, p, __float_as_int(w));
        }
    } else if (i < PF_H) {
        int i2 = i - PF_FILL;
        int node = i2 >> 5;
        int j = i2 & 31;                    // float4 index within row
        float4 f = ((const float4*)h)[(size_t)node * 32 + j];
        float ff[4] = {f.x, f.y, f.z, f.w};
        u32 hw[2];
#pragma unroll
        for (int q = 0; q < 2; q++) {
            __half h0 = __float2half(ff[2 * q]);
            __half h1 = __float2half(ff[2 * q + 1]);
            hw[q] = (u32)__half_as_ushort(h0) | ((u32)__half_as_ushort(h1) << 16);
        }
        int chunk = j >> 4;
        int jj = j & 15;
        int u = jj >> 1, half = jj & 1;
        size_t db = (size_t)node * 1024 + chunk * 128 + ((u ^ (node & 7)) << 4) + half * 8;
        *(uint2*)((char*)g_Xh + db) = make_uint2(hw[0], hw[1]);
    } else if (i < PF_END) {
        int i2 = i - PF_H;
        int n = i2 >> 9;
        int c = i2 & 511;
        float v = W[n * 640 + c];
        if (c >= 128 && c < 256) v += W[n * 640 + c + 384];
        int chunk = c >> 6, kk = c & 63;
        int u = kk >> 3, sub = kk & 7;
        size_t db = (size_t)chunk * 16384 + n * 128 + ((u ^ (n & 7)) << 4) + sub * 2;
        *(__half*)((char*)g_Wh + db) = __float2half(v);
    }
}

// ---------------------------------------------------------------------------
// Aggregation: one warp per dst node; 3 direction channels in registers;
// fp32 h gather (proven R12 path); overflow inline; output fp16 X chunks 2-7
// (pre-permuted). Resets g_cnt[d] after use so the next launch starts clean.
// ---------------------------------------------------------------------------
__global__ __launch_bounds__(256) void agg_kernel(const float4* __restrict__ h4) {
    int idx = blockIdx.x * blockDim.x + threadIdx.x;
    int d = idx >> 5;
    int lane = idx & 31;
    if (d >= N_NODES) return;
    int deg = g_cnt[d];
    float4 a[3];
#pragma unroll
    for (int p = 0; p < 3; p++) a[p] = make_float4(0.f, 0.f, 0.f, 0.f);

    const u64* rp = g_rec + (size_t)d * CAP;
    int nrec = deg > CAP ? CAP : deg;
#pragma unroll 4
    for (int i = 0; i < nrec; i++) {
        u64 rec = __ldg(rp + i);
        unsigned lo = (unsigned)rec;
        float w = __uint_as_float((unsigned)(rec >> 32));
        int s = lo & 0xFFFF;
        int p = lo >> 16;
        float4 hv = h4[(size_t)s * 32 + lane];
        if (p == 0)      { a[0].x += hv.x * w; a[0].y += hv.y * w; a[0].z += hv.z * w; a[0].w += hv.w * w; }
        else if (p == 1) { a[1].x += hv.x * w; a[1].y += hv.y * w; a[1].z += hv.z * w; a[1].w += hv.w * w; }
        else             { a[2].x += hv.x * w; a[2].y += hv.y * w; a[2].z += hv.z * w; a[2].w += hv.w * w; }
    }
    if (deg > CAP) {   // inline overflow fixup (normally zero iterations)
        int n = g_cnt[N_NODES];
        if (n > OVF_CAP) n = OVF_CAP;
        for (int i = 0; i < n; i++) {
            int4 r = g_ovf[i];
            if (r.y != d) continue;
            float w = __int_as_float(r.w);
            float4 hv = h4[(size_t)r.x * 32 + lane];
            int p = r.z;
            if (p == 0)      { a[0].x += hv.x * w; a[0].y += hv.y * w; a[0].z += hv.z * w; a[0].w += hv.w * w; }
            else if (p == 1) { a[1].x += hv.x * w; a[1].y += hv.y * w; a[1].z += hv.z * w; a[1].w += hv.w * w; }
            else             { a[2].x += hv.x * w; a[2].y += hv.y * w; a[2].z += hv.z * w; a[2].w += hv.w * w; }
        }
    }
    if (lane == 0) g_cnt[d] = 0;   // clean slate for next launch

    int chunkBase = 2 + (lane >> 4);
    int u = (lane & 15) >> 1, half = lane & 1;
    size_t db0 = (size_t)d * 1024 + ((u ^ (d & 7)) << 4) + half * 8;
#pragma unroll
    for (int p = 0; p < 3; p++) {
        float ff[4] = {a[p].x, a[p].y, a[p].z, a[p].w};
        u32 hw[2];
#pragma unroll
        for (int q = 0; q < 2; q++) {
            __half h0 = __float2half(ff[2 * q]);
            __half h1 = __float2half(ff[2 * q + 1]);
            hw[q] = (u32)__half_as_ushort(h0) | ((u32)__half_as_ushort(h1) << 16);
        }
        size_t db = db0 + (chunkBase + 2 * p) * 128;
        *(uint2*)((char*)g_Xh + db) = make_uint2(hw[0], hw[1]);
    }
}

// ---------------------------------------------------------------------------
// Single-pass fp16 mma.sync GEMM + bias + LayerNorm + ReLU.
// z = fp16(X) * fp16(W), fp32 accum. CTA 128x128, 8 warps 4(M)x2(N).
// X AND B double-buffered cp.async; 2 CTAs/SM. Smem 69120 B.
// ---------------------------------------------------------------------------
#define SM_BIAS 0
#define SM_GAMMA 512
#define SM_BETA 1024
#define SM_ROWS 1536
#define SM_X 3584                       // 2 bufs x 16K (Xh)
#define SM_B (SM_X + 32768)             // 2 bufs x 16K (Wh)
#define SMEM_GEMM (SM_B + 32768)        // 69120 B

__device__ __forceinline__ void mma_f16(float* c, u32 a0, u32 a1, u32 a2, u32 a3,
                                        u32 b0, u32 b1) {
    asm volatile(
        "mma.sync.aligned.m16n8k16.row.col.f32.f16.f16.f32 "
        "{%0,%1,%2,%3}, {%4,%5,%6,%7}, {%8,%9}, {%0,%1,%2,%3};"
        : "+f"(c[0]), "+f"(c[1]), "+f"(c[2]), "+f"(c[3])
        : "r"(a0), "r"(a1), "r"(a2), "r"(a3), "r"(b0), "r"(b1));
}
#define LDSM4(r0, r1, r2, r3, addr) \
    asm volatile("ldmatrix.sync.aligned.m8n8.x4.shared.b16 {%0,%1,%2,%3}, [%4];" \
                 : "=r"(r0), "=r"(r1), "=r"(r2), "=r"(r3) : "r"(addr))
#define CP16(dst, src) \
    asm volatile("cp.async.cg.shared.global [%0], [%1], 16;" :: "r"(dst), "l"(src))
#define CP_COMMIT() asm volatile("cp.async.commit_group;" ::: "memory")
#define CP_WAIT1() asm volatile("cp.async.wait_group 1;" ::: "memory")
#define CP_WAIT0() asm volatile("cp.async.wait_group 0;" ::: "memory")

__device__ __forceinline__ u32 smem_u32(const void* p) {
    u32 a;
    asm("{ .reg .u64 t; cvta.to.shared.u64 t, %1; cvt.u32.u64 %0, t; }"
        : "=r"(a) : "l"(p));
    return a;
}

__global__ __launch_bounds__(256, 2) void gemm_ln_kernel(
    const float* __restrict__ bias,
    const float* __restrict__ gamma,
    const float* __restrict__ beta,
    float* __restrict__ out) {

    extern __shared__ char smem[];
    const u32 sbase = smem_u32(smem);
    const int tid = threadIdx.x;
    const int lane = tid & 31;
    const int wid = tid >> 5;
    const int warpM = wid >> 1;
    const int warpN = wid & 1;
    const int nodeBase = blockIdx.x * 128;
    const int laneRow = lane >> 2;
    const int laneK2 = (lane & 3) * 2;
    const int lr = lane & 7;
    const int lg = lane >> 3;

    if (blockIdx.x == 0 && tid == 0) g_cnt[N_NODES] = 0;  // reset overflow ctr

    const int aRowB = warpM * 32 + (lg & 1) * 8 + lr;
    const int aUG = lg >> 1;
    const int aSw = aRowB & 7;
    const int bRowB = warpN * 64 + (lg >> 1) * 8 + lr;
    const int bUG = lg & 1;
    const int bSw = bRowB & 7;

    if (tid < 128) {
        *(float*)(smem + SM_BIAS + tid * 4) = bias[tid];
        *(float*)(smem + SM_GAMMA + tid * 4) = gamma[tid];
        *(float*)(smem + SM_BETA + tid * 4) = beta[tid];
    }

    float acc[2][8][4];
#pragma unroll
    for (int mt = 0; mt < 2; mt++)
#pragma unroll
        for (int nt = 0; nt < 8; nt++)
#pragma unroll
            for (int q = 0; q < 4; q++) acc[mt][nt][q] = 0.f;

    const size_t xrowbase = (size_t)nodeBase * 1024;
    auto issue_chunk = [&](int c) {
        int buf = c & 1;
        u32 dx = sbase + SM_X + buf * 16384;
#pragma unroll
        for (int it = 0; it < 4; it++) {
            int u = tid + it * 256;          // 0..1023 16B units
            int row = u >> 3, un = u & 7;
            size_t so = xrowbase + (size_t)row * 1024 + c * 128 + un * 16;
            CP16(dx + row * 128 + un * 16, (const char*)g_Xh + so);
        }
        u32 db = sbase + SM_B + buf * 16384;
#pragma unroll
        for (int it = 0; it < 4; it++) {
            int u = tid + it * 256;          // 0..1023 16B units
            size_t so = (size_t)c * 16384 + u * 16;
            CP16(db + u * 16, (const char*)g_Wh + so);
        }
        CP_COMMIT();
    };

    issue_chunk(0);
    issue_chunk(1);

    for (int c = 0; c < 8; c++) {
        if (c < 7) CP_WAIT1(); else CP_WAIT0();
        __syncthreads();

        const u32 xh = sbase + SM_X + (c & 1) * 16384;
        const u32 bh = sbase + SM_B + (c & 1) * 16384;
#pragma unroll
        for (int ks = 0; ks < 4; ks++) {
            u32 ah[2][4], bf[8][2];
            const int aCol = ((2 * ks + aUG) ^ aSw) << 4;
            const int bCol = ((2 * ks + bUG) ^ bSw) << 4;
#pragma unroll
            for (int mt = 0; mt < 2; mt++) {
                u32 ro = (u32)((aRowB + mt * 16) * 128 + aCol);
                LDSM4(ah[mt][0], ah[mt][1], ah[mt][2], ah[mt][3], xh + ro);
            }
#pragma unroll
            for (int ntp = 0; ntp < 4; ntp++) {
                u32 ro = (u32)((bRowB + ntp * 16) * 128 + bCol);
                LDSM4(bf[2 * ntp][0], bf[2 * ntp][1],
                      bf[2 * ntp + 1][0], bf[2 * ntp + 1][1], bh + ro);
            }
#pragma unroll
            for (int mt = 0; mt < 2; mt++)
#pragma unroll
                for (int nt = 0; nt < 8; nt++)
                    mma_f16(acc[mt][nt], ah[mt][0], ah[mt][1], ah[mt][2], ah[mt][3],
                            bf[nt][0], bf[nt][1]);
        }
        __syncthreads();
        if (c < 6) issue_chunk(c + 2);
    }

    // ---- Epilogue: bias + LN sums from fragments ----
    const float* sbias = (const float*)(smem + SM_BIAS);
    float s1[2][2], s2[2][2];
#pragma unroll
    for (int mt = 0; mt < 2; mt++) { s1[mt][0] = s1[mt][1] = s2[mt][0] = s2[mt][1] = 0.f; }
#pragma unroll
    for (int mt = 0; mt < 2; mt++)
#pragma unroll
        for (int nt = 0; nt < 8; nt++) {
            int j0 = warpN * 64 + nt * 8 + laneK2;
            float b0 = sbias[j0], b1 = sbias[j0 + 1];
            acc[mt][nt][0] += b0; acc[mt][nt][1] += b1;
            acc[mt][nt][2] += b0; acc[mt][nt][3] += b1;
            s1[mt][0] += acc[mt][nt][0] + acc[mt][nt][1];
            s2[mt][0] += acc[mt][nt][0] * acc[mt][nt][0] + acc[mt][nt][1] * acc[mt][nt][1];
            s1[mt][1] += acc[mt][nt][2] + acc[mt][nt][3];
            s2[mt][1] += acc[mt][nt][2] * acc[mt][nt][2] + acc[mt][nt][3] * acc[mt][nt][3];
        }
#pragma unroll
    for (int mt = 0; mt < 2; mt++)
#pragma unroll
        for (int rh = 0; rh < 2; rh++) {
            s1[mt][rh] += __shfl_xor_sync(0xFFFFFFFF, s1[mt][rh], 1);
            s1[mt][rh] += __shfl_xor_sync(0xFFFFFFFF, s1[mt][rh], 2);
            s2[mt][rh] += __shfl_xor_sync(0xFFFFFFFF, s2[mt][rh], 1);
            s2[mt][rh] += __shfl_xor_sync(0xFFFFFFFF, s2[mt][rh], 2);
        }
    if ((lane & 3) == 0) {
#pragma unroll
        for (int mt = 0; mt < 2; mt++)
#pragma unroll
            for (int rh = 0; rh < 2; rh++) {
                int row = warpM * 32 + mt * 16 + rh * 8 + laneRow;
                *(float2*)(smem + SM_ROWS + (warpN * 128 + row) * 8) =
                    make_float2(s1[mt][rh], s2[mt][rh]);
            }
    }
    __syncthreads();

    const float* sg = (const float*)(smem + SM_GAMMA);
    const float* sbeta = (const float*)(smem + SM_BETA);
#pragma unroll
    for (int mt = 0; mt < 2; mt++)
#pragma unroll
        for (int rh = 0; rh < 2; rh++) {
            int row = warpM * 32 + mt * 16 + rh * 8 + laneRow;
            float2 p0 = *(const float2*)(smem + SM_ROWS + row * 8);
            float2 p1 = *(const float2*)(smem + SM_ROWS + (128 + row) * 8);
            float mu = (p0.x + p1.x) * (1.0f / 128.0f);
            float var = (p0.y + p1.y) * (1.0f / 128.0f) - mu * mu;
            float rs = rsqrtf(var + 1e-5f);
            int gn = nodeBase + row;
            if (gn < N_NODES) {
#pragma unroll
                for (int nt = 0; nt < 8; nt++) {
                    int j0 = warpN * 64 + nt * 8 + laneK2;
                    float z0 = acc[mt][nt][rh * 2 + 0];
                    float z1 = acc[mt][nt][rh * 2 + 1];
                    float2 o;
                    o.x = fmaxf((z0 - mu) * rs * sg[j0] + sbeta[j0], 0.f);
                    o.y = fmaxf((z1 - mu) * rs * sg[j0 + 1] + sbeta[j0 + 1], 0.f);
                    *(float2*)(out + (size_t)gn * 128 + j0) = o;
                }
            }
        }
}

extern "C" void kernel_launch(void* const* d_in, const int* in_sizes, int n_in,
                              void* d_out, int out_size) {
    const float* h     = (const float*)d_in[0];
    const float* dist  = (const float*)d_in[1];
    const float* W     = (const float*)d_in[2];
    const float* b     = (const float*)d_in[3];
    const float* gamma = (const float*)d_in[4];
    const float* beta  = (const float*)d_in[5];
    const int* src     = (const int*)d_in[6];
    const int* dst     = (const int*)d_in[7];
    const int* pos     = (const int*)d_in[8];
    float* out = (float*)d_out;

    cudaFuncSetAttribute(gemm_ln_kernel,
                         cudaFuncAttributeMaxDynamicSharedMemorySize, SMEM_GEMM);

    prepfill_kernel<<<(PF_END + 255) / 256, 256>>>(h, W, dist, src, dst, pos);

    agg_kernel<<<(N_NODES * 32 + 255) / 256, 256>>>((const float4*)h);

    gemm_ln_kernel<<<(N_NODES + 127) / 128, 256, SMEM_GEMM>>>(b, gamma, beta, out);
}